// round 3
// baseline (speedup 1.0000x reference)
#include <cuda_runtime.h>
#include <stdint.h>
#include <math.h>

// Problem constants
#define BB 8
#define HH 640
#define WW 640
#define NPIX (HH*WW)          // 409600 pixels per sample
#define PPB 4096              // pixels per block in big passes
#define BPS (NPIX/PPB)        // 100 blocks per sample
#define NBLK (BB*BPS)         // 800 blocks
#define NT 256
#define NBINS 65536

// -------- device scratch (no allocations allowed) --------
__device__ double g_cls, g_norm, g_ang;
__device__ unsigned long long g_angc;
__device__ double g_pos_sum[BB], g_neg_sum[BB], g_gt_sum[BB], g_posi[BB], g_nega[BB];
__device__ unsigned int g_pos_cnt[BB];
__device__ int g_mode[BB];                 // 0 = resolved (fast path), 1 = needs radix select
__device__ long long g_k_total[BB], g_k_rem[BB];
__device__ unsigned int g_sel16[BB];
__device__ unsigned int g_h1[BB*NBINS];    // level-1 histogram (counts, top 16 bits)
__device__ unsigned int g_h2c[BB*NBINS];   // level-2 histogram counts (low 16 bits)
__device__ float        g_h2s[BB*NBINS];   // level-2 histogram value sums

// ---------------- init: zero accumulators + histograms ----------------
__global__ void __launch_bounds__(NT) k_init() {
    size_t i = (size_t)blockIdx.x * blockDim.x + threadIdx.x;
    // 8*65536 = 524288 words per array; grid 512x256 = 131072 threads -> 4 uint4 stores each
    uint4 z4 = make_uint4(0u, 0u, 0u, 0u);
    size_t n4 = (size_t)BB * NBINS / 4;
    size_t stride = (size_t)gridDim.x * blockDim.x;
    for (size_t j = i; j < n4; j += stride) {
        ((uint4*)g_h1)[j]  = z4;
        ((uint4*)g_h2c)[j] = z4;
        ((uint4*)g_h2s)[j] = z4;
    }
    if (i < BB) {
        g_pos_sum[i] = 0.0; g_neg_sum[i] = 0.0; g_gt_sum[i] = 0.0;
        g_posi[i] = 0.0; g_nega[i] = 0.0;
        g_pos_cnt[i] = 0u; g_mode[i] = 0;
        g_k_total[i] = 0; g_k_rem[i] = 0; g_sel16[i] = 0u;
    }
    if (i == 0) { g_cls = 0.0; g_norm = 0.0; g_ang = 0.0; g_angc = 0ull; }
}

__device__ __forceinline__ double warp_red(double v) {
    #pragma unroll
    for (int o = 16; o > 0; o >>= 1) v += __shfl_down_sync(0xffffffffu, v, o);
    return v;
}

// ---------------- main fused pass ----------------
__global__ void __launch_bounds__(NT) k_main(
    const float* __restrict__ fy,      // [B,4,H,W]
    const float* __restrict__ tmask,   // [B,H,W] float
    const int*   __restrict__ trm,     // [B,H,W] int
    const float* __restrict__ distf,   // [B,H,W]
    const float* __restrict__ dirf,    // [B,2,H,W]
    const float* __restrict__ wm)      // [B,H,W]
{
    const int s    = blockIdx.x / BPS;
    const int tile = blockIdx.x % BPS;

    const float4* c0 = (const float4*)(fy + ((size_t)s*4 + 0) * NPIX);
    const float4* c1 = (const float4*)(fy + ((size_t)s*4 + 1) * NPIX);
    const float4* c2 = (const float4*)(fy + ((size_t)s*4 + 2) * NPIX);
    const float4* c3 = (const float4*)(fy + ((size_t)s*4 + 3) * NPIX);
    const float4* gx4p = (const float4*)(dirf + ((size_t)s*2 + 0) * NPIX);
    const float4* gy4p = (const float4*)(dirf + ((size_t)s*2 + 1) * NPIX);
    const float4* tm4p = (const float4*)(tmask + (size_t)s * NPIX);
    const float4* df4p = (const float4*)(distf + (size_t)s * NPIX);
    const float4* wm4p = (const float4*)(wm    + (size_t)s * NPIX);
    const int4*   tr4p = (const int4*)  (trm   + (size_t)s * NPIX);

    float cls_a = 0.f, pos_a = 0.f, neg_a = 0.f, norm_a = 0.f, ang_a = 0.f;
    int posc = 0, angc = 0;

    #pragma unroll
    for (int j = 0; j < 4; j++) {
        int i4 = tile * (PPB/4) + j * NT + threadIdx.x;
        float4 p4 = c0[i4], q4 = c1[i4], x4 = c2[i4], y4 = c3[i4];
        float4 g1 = gx4p[i4], g2 = gy4p[i4];
        float4 t4 = tm4p[i4], d4 = df4p[i4], w4 = wm4p[i4];
        int4   r4 = tr4p[i4];

        #pragma unroll
        for (int e = 0; e < 4; e++) {
            float p   = ((const float*)&p4)[e];
            float d1  = ((const float*)&q4)[e];
            float px  = ((const float*)&x4)[e];
            float py  = ((const float*)&y4)[e];
            float gx  = ((const float*)&g1)[e];
            float gy  = ((const float*)&g2)[e];
            float tm  = ((const float*)&t4)[e];
            float dfv = ((const float*)&d4)[e];
            float w   = ((const float*)&w4)[e];
            int   tr  = ((const int*)&r4)[e];

            // cls: masked BCE
            float pc  = fminf(fmaxf(p, 1e-7f), 1.0f - 1e-7f);
            float bce = (tr > 0) ? -logf(pc) : -logf(1.0f - pc);
            cls_a += bce * tm;

            // distance pre-loss + pos/neg split
            float diff = d1 - dfv;
            float pre  = diff * diff * tm;
            bool  pos  = (dfv >= 1e-3f);
            if (pos) { pos_a += pre; posc++; } else { neg_a += pre; }

            // flux: gt normalize (with reference eps)
            float sg = gx*gx + gy*gy;
            float gl = sqrtf(sg);
            float ig = 1.0f / (gl + 1e-6f);
            float gtx = gx * ig, gty = gy * ig;
            float ex = px - gtx, ey = py - gty;
            norm_a += w * 0.5f * (ex*ex + ey*ey) * tm;

            // angle (masked)
            if (tm > 0.f && tr > 0) {
                float sp = px*px + py*py;
                float pl = sqrtf(sp);
                float ip = 1.0f / (pl + 1e-6f);
                float pnx = px * ip, pny = py * ip;
                float na = sqrtf(pnx*pnx + pny*pny);
                float nb = sqrtf(gtx*gtx + gty*gty);
                float cosv = (pnx*gtx + pny*gty) / fmaxf(na*nb, 1e-8f);
                ang_a += 1.0f - cosv;
                angc++;
            }
        }
    }

    // block reduction: 7 quantities -> double atomics
    double v0 = warp_red((double)cls_a);
    double v1 = warp_red((double)pos_a);
    double v2 = warp_red((double)neg_a);
    double v3 = warp_red((double)posc);
    double v4 = warp_red((double)norm_a);
    double v5 = warp_red((double)ang_a);
    double v6 = warp_red((double)angc);

    __shared__ double sh[8][7];
    int wid = threadIdx.x >> 5, lid = threadIdx.x & 31;
    if (lid == 0) {
        sh[wid][0]=v0; sh[wid][1]=v1; sh[wid][2]=v2; sh[wid][3]=v3;
        sh[wid][4]=v4; sh[wid][5]=v5; sh[wid][6]=v6;
    }
    __syncthreads();
    if (threadIdx.x == 0) {
        double t[7] = {0,0,0,0,0,0,0};
        #pragma unroll
        for (int k = 0; k < 8; k++)
            #pragma unroll
            for (int q = 0; q < 7; q++) t[q] += sh[k][q];
        atomicAdd(&g_cls, t[0]);
        atomicAdd(&g_pos_sum[s], t[1]);
        atomicAdd(&g_neg_sum[s], t[2]);
        atomicAdd(&g_pos_cnt[s], (unsigned int)(t[3] + 0.5));
        atomicAdd(&g_norm, t[4]);
        atomicAdd(&g_ang, t[5]);
        atomicAdd(&g_angc, (unsigned long long)(t[6] + 0.5));
    }
}

// ---------------- decide fast vs select path per sample ----------------
__global__ void k_decide() {
    int s = threadIdx.x;
    if (s >= BB) return;
    long long npos = (long long)g_pos_cnt[s];
    long long nneg = (long long)NPIX - npos;
    if (npos > 0) {
        long long k = 3 * npos; if (nneg < k) k = nneg;
        g_posi[s] = g_pos_sum[s] / (double)(npos > 1 ? npos : 1);
        if (k <= 0)            { g_nega[s] = 0.0; g_mode[s] = 0; }
        else if (k == nneg)    { g_nega[s] = g_neg_sum[s] / (double)k; g_mode[s] = 0; }
        else                   { g_mode[s] = 1; g_k_total[s] = k; g_k_rem[s] = k; }
    } else {
        // top-100 fallback over all pre values (no positives exist in this case)
        g_posi[s] = 0.0; g_mode[s] = 1; g_k_total[s] = 100; g_k_rem[s] = 100;
    }
}

// transformed key: pos pixels -> 0 (sorts below all), neg -> bits(pre)+1 (monotone, pre>=0)
__device__ __forceinline__ unsigned key_of(float d1, float dfv, float tm) {
    float diff = d1 - dfv;
    float pre  = diff * diff * tm;
    return (dfv >= 1e-3f) ? 0u : (__float_as_uint(pre) + 1u);
}

// ---------------- radix-select level 1 (top 16 bits) ----------------
__global__ void __launch_bounds__(NT) k_hist1(
    const float* __restrict__ fy, const float* __restrict__ tmask,
    const float* __restrict__ distf)
{
    int s = blockIdx.x / BPS;
    if (g_mode[s] != 1) return;
    int tile = blockIdx.x % BPS;
    const float* ch1 = fy + ((size_t)s*4 + 1) * NPIX;
    const float* tm  = tmask + (size_t)s * NPIX;
    const float* df  = distf + (size_t)s * NPIX;
    #pragma unroll 4
    for (int j = 0; j < 16; j++) {
        int i = tile * PPB + j * NT + threadIdx.x;
        unsigned u = key_of(__ldg(ch1 + i), __ldg(df + i), __ldg(tm + i));
        atomicAdd(&g_h1[s * NBINS + (u >> 16)], 1u);
    }
}

__global__ void __launch_bounds__(NT) k_scan1() {
    int s = blockIdx.x;
    if (g_mode[s] != 1) return;
    __shared__ unsigned long long chc[NT];
    const unsigned* h = g_h1 + (size_t)s * NBINS;
    int t = threadIdx.x;
    unsigned long long c = 0;
    for (int i = 0; i < 256; i++) c += h[t * 256 + i];
    chc[t] = c;
    __syncthreads();
    if (t == 0) {
        long long krem = g_k_rem[s];
        long long above = 0;
        int cs = 255;
        for (int ch = 255; ch >= 0; ch--) {
            if (above + (long long)chc[ch] >= krem) { cs = ch; break; }
            above += (long long)chc[ch];
        }
        int bsel = cs * 256;
        for (int i = 255; i >= 0; i--) {
            int b = cs * 256 + i;
            long long cc = (long long)h[b];
            if (above + cc >= krem) { bsel = b; break; }
            above += cc;
        }
        g_sel16[s] = (unsigned)(bsel >> 8) == 0u ? (unsigned)bsel : (unsigned)bsel; // keep exact bin
        g_sel16[s] = (unsigned)bsel;
        g_k_rem[s] = krem - above;   // still to take from inside selected top-16 bin
    }
}

// ---------------- radix-select level 2 (low 16 bits) + sum of strictly-greater ----------------
__global__ void __launch_bounds__(NT) k_hist2(
    const float* __restrict__ fy, const float* __restrict__ tmask,
    const float* __restrict__ distf)
{
    int s = blockIdx.x / BPS;
    if (g_mode[s] != 1) return;
    int tile = blockIdx.x % BPS;
    unsigned sel = g_sel16[s];
    const float* ch1 = fy + ((size_t)s*4 + 1) * NPIX;
    const float* tm  = tmask + (size_t)s * NPIX;
    const float* df  = distf + (size_t)s * NPIX;
    double gt_local = 0.0;
    for (int j = 0; j < 16; j++) {
        int i = tile * PPB + j * NT + threadIdx.x;
        float d1 = __ldg(ch1 + i), dfv = __ldg(df + i), t = __ldg(tm + i);
        float diff = d1 - dfv;
        float pre  = diff * diff * t;
        unsigned u = (dfv >= 1e-3f) ? 0u : (__float_as_uint(pre) + 1u);
        unsigned top = u >> 16;
        if (top == sel) {
            atomicAdd(&g_h2c[s * NBINS + (u & 0xffffu)], 1u);
            atomicAdd(&g_h2s[s * NBINS + (u & 0xffffu)], pre);
        } else if (top > sel) {
            gt_local += (double)pre;
        }
    }
    double v = warp_red(gt_local);
    __shared__ double sh[8];
    int wid = threadIdx.x >> 5, lid = threadIdx.x & 31;
    if (lid == 0) sh[wid] = v;
    __syncthreads();
    if (threadIdx.x == 0) {
        double tot = 0; for (int k = 0; k < 8; k++) tot += sh[k];
        atomicAdd(&g_gt_sum[s], tot);
    }
}

// ---------------- finalize: resolve selects, combine all losses ----------------
__global__ void __launch_bounds__(NT) k_final(float* __restrict__ out) {
    __shared__ unsigned long long chC[NT];
    __shared__ double chS[NT];
    __shared__ double persample[BB];

    for (int s = 0; s < BB; s++) {
        if (g_mode[s] == 1) {
            const unsigned* hc = g_h2c + (size_t)s * NBINS;
            const float*    hs = g_h2s + (size_t)s * NBINS;
            int t = threadIdx.x;
            unsigned long long c = 0; double su = 0;
            for (int i = 0; i < 256; i++) { c += hc[t*256 + i]; su += (double)hs[t*256 + i]; }
            chC[t] = c; chS[t] = su;
            __syncthreads();
            if (t == 0) {
                long long krem = g_k_rem[s];
                long long above = 0; double asum = 0; int cs = 255;
                for (int ch = 255; ch >= 0; ch--) {
                    if (above + (long long)chC[ch] >= krem) { cs = ch; break; }
                    above += (long long)chC[ch]; asum += chS[ch];
                }
                int bsel = cs * 256;
                for (int i = 255; i >= 0; i--) {
                    int b = cs * 256 + i;
                    long long cc = (long long)hc[b];
                    if (above + cc >= krem) { bsel = b; break; }
                    above += cc; asum += (double)hs[b];
                }
                unsigned pivot_u = (g_sel16[s] << 16) | (unsigned)bsel;
                float pivotf = __uint_as_float(pivot_u - 1u);
                long long take = krem - above;
                double negsum = g_gt_sum[s] + asum + (double)take * (double)pivotf;
                long long kt = g_k_total[s]; if (kt < 1) kt = 1;
                persample[s] = g_posi[s] + negsum / (double)kt;
            }
            __syncthreads();
        } else {
            if (threadIdx.x == 0) persample[s] = g_posi[s] + g_nega[s];
            __syncthreads();
        }
    }

    if (threadIdx.x == 0) {
        double dis = 0; for (int s = 0; s < BB; s++) dis += persample[s];
        dis /= (double)BB;
        double cls  = g_cls  / ((double)BB * (double)NPIX);
        double norm = g_norm / ((double)BB * (double)HH);
        unsigned long long ac = g_angc; if (ac < 1ull) ac = 1ull;
        double ang  = g_ang / (double)ac;
        double total = cls + 3.0 * dis + 0.5 * (norm + ang);
        out[0] = (float)total;
    }
}

// ---------------- launcher ----------------
extern "C" void kernel_launch(void* const* d_in, const int* in_sizes, int n_in,
                              void* d_out, int out_size) {
    const float* fy    = (const float*)d_in[0];
    const float* tmask = (const float*)d_in[1];
    const int*   trm   = (const int*)  d_in[2];
    const float* distf = (const float*)d_in[3];
    const float* dirf  = (const float*)d_in[4];
    const float* wm    = (const float*)d_in[5];
    float* out = (float*)d_out;

    k_init<<<512, NT>>>();
    k_main<<<NBLK, NT>>>(fy, tmask, trm, distf, dirf, wm);
    k_decide<<<1, 32>>>();
    k_hist1<<<NBLK, NT>>>(fy, tmask, distf);
    k_scan1<<<BB, NT>>>();
    k_hist2<<<NBLK, NT>>>(fy, tmask, distf);
    k_final<<<1, NT>>>(out);
}

// round 4
// speedup vs baseline: 1.2386x; 1.2386x over previous
#include <cuda_runtime.h>
#include <stdint.h>
#include <math.h>

// Problem constants
#define BB 8
#define HH 640
#define WW 640
#define NPIX (HH*WW)          // 409600 pixels per sample
#define PPB 4096              // pixels per block in main pass
#define BPS (NPIX/PPB)        // 100 blocks per sample
#define NBLK (BB*BPS)         // 800 blocks
#define NT 256

// -------- device scratch: per-block partials (plain stores, no init needed) --------
__device__ double g_p_cls [NBLK];
__device__ double g_p_pos [NBLK];
__device__ double g_p_neg [NBLK];
__device__ double g_p_posc[NBLK];
__device__ double g_p_norm[NBLK];
__device__ double g_p_ang [NBLK];
__device__ double g_p_angc[NBLK];

__device__ __forceinline__ double warp_red(double v) {
    #pragma unroll
    for (int o = 16; o > 0; o >>= 1) v += __shfl_down_sync(0xffffffffu, v, o);
    return v;
}

// ---------------- main fused pass: 1 read of every input byte ----------------
__global__ void __launch_bounds__(NT) k_main(
    const float* __restrict__ fy,      // [B,4,H,W]
    const float* __restrict__ tmask,   // [B,H,W] float
    const int*   __restrict__ trm,     // [B,H,W] int
    const float* __restrict__ distf,   // [B,H,W]
    const float* __restrict__ dirf,    // [B,2,H,W]
    const float* __restrict__ wm)      // [B,H,W]
{
    const int s    = blockIdx.x / BPS;
    const int tile = blockIdx.x % BPS;

    const float4* c0 = (const float4*)(fy + ((size_t)s*4 + 0) * NPIX);
    const float4* c1 = (const float4*)(fy + ((size_t)s*4 + 1) * NPIX);
    const float4* c2 = (const float4*)(fy + ((size_t)s*4 + 2) * NPIX);
    const float4* c3 = (const float4*)(fy + ((size_t)s*4 + 3) * NPIX);
    const float4* gx4p = (const float4*)(dirf + ((size_t)s*2 + 0) * NPIX);
    const float4* gy4p = (const float4*)(dirf + ((size_t)s*2 + 1) * NPIX);
    const float4* tm4p = (const float4*)(tmask + (size_t)s * NPIX);
    const float4* df4p = (const float4*)(distf + (size_t)s * NPIX);
    const float4* wm4p = (const float4*)(wm    + (size_t)s * NPIX);
    const int4*   tr4p = (const int4*)  (trm   + (size_t)s * NPIX);

    float cls_a = 0.f, pos_a = 0.f, neg_a = 0.f, norm_a = 0.f, ang_a = 0.f;
    int posc = 0, angc = 0;

    #pragma unroll
    for (int j = 0; j < 4; j++) {
        int i4 = tile * (PPB/4) + j * NT + threadIdx.x;
        float4 p4 = c0[i4], q4 = c1[i4], x4 = c2[i4], y4 = c3[i4];
        float4 g1 = gx4p[i4], g2 = gy4p[i4];
        float4 t4 = tm4p[i4], d4 = df4p[i4], w4 = wm4p[i4];
        int4   r4 = tr4p[i4];

        #pragma unroll
        for (int e = 0; e < 4; e++) {
            float p   = ((const float*)&p4)[e];
            float d1  = ((const float*)&q4)[e];
            float px  = ((const float*)&x4)[e];
            float py  = ((const float*)&y4)[e];
            float gx  = ((const float*)&g1)[e];
            float gy  = ((const float*)&g2)[e];
            float tm  = ((const float*)&t4)[e];
            float dfv = ((const float*)&d4)[e];
            float w   = ((const float*)&w4)[e];
            int   tr  = ((const int*)&r4)[e];

            // cls: masked BCE
            float pc  = fminf(fmaxf(p, 1e-7f), 1.0f - 1e-7f);
            float bce = (tr > 0) ? -logf(pc) : -logf(1.0f - pc);
            cls_a += bce * tm;

            // distance pre-loss + pos/neg split
            float diff = d1 - dfv;
            float pre  = diff * diff * tm;
            bool  pos  = (dfv >= 1e-3f);
            if (pos) { pos_a += pre; posc++; } else { neg_a += pre; }

            // flux: gt normalize (reference eps)
            float sg = gx*gx + gy*gy;
            float gl = sqrtf(sg);
            float ig = 1.0f / (gl + 1e-6f);
            float gtx = gx * ig, gty = gy * ig;
            float ex = px - gtx, ey = py - gty;
            norm_a += w * 0.5f * (ex*ex + ey*ey) * tm;

            // angle (masked)
            if (tm > 0.f && tr > 0) {
                float sp = px*px + py*py;
                float pl = sqrtf(sp);
                float ip = 1.0f / (pl + 1e-6f);
                float pnx = px * ip, pny = py * ip;
                float na = sqrtf(pnx*pnx + pny*pny);
                float nb = sqrtf(gtx*gtx + gty*gty);
                float cosv = (pnx*gtx + pny*gty) / fmaxf(na*nb, 1e-8f);
                ang_a += 1.0f - cosv;
                angc++;
            }
        }
    }

    // block reduction -> per-block partial slots (plain stores)
    double v0 = warp_red((double)cls_a);
    double v1 = warp_red((double)pos_a);
    double v2 = warp_red((double)neg_a);
    double v3 = warp_red((double)posc);
    double v4 = warp_red((double)norm_a);
    double v5 = warp_red((double)ang_a);
    double v6 = warp_red((double)angc);

    __shared__ double sh[8][7];
    int wid = threadIdx.x >> 5, lid = threadIdx.x & 31;
    if (lid == 0) {
        sh[wid][0]=v0; sh[wid][1]=v1; sh[wid][2]=v2; sh[wid][3]=v3;
        sh[wid][4]=v4; sh[wid][5]=v5; sh[wid][6]=v6;
    }
    __syncthreads();
    if (threadIdx.x == 0) {
        double t[7] = {0,0,0,0,0,0,0};
        #pragma unroll
        for (int k = 0; k < 8; k++)
            #pragma unroll
            for (int q = 0; q < 7; q++) t[q] += sh[k][q];
        int b = blockIdx.x;
        g_p_cls [b] = t[0];
        g_p_pos [b] = t[1];
        g_p_neg [b] = t[2];
        g_p_posc[b] = t[3];
        g_p_norm[b] = t[4];
        g_p_ang [b] = t[5];
        g_p_angc[b] = t[6];
    }
}

// transformed key: pos pixels -> 0 (sorts last), neg -> bits(pre)+1 (monotone, pre>=0)
__device__ __forceinline__ unsigned key_of(float d1, float dfv, float tm) {
    float diff = d1 - dfv;
    float pre  = diff * diff * tm;
    return (dfv >= 1e-3f) ? 0u : (__float_as_uint(pre) + 1u);
}

// ---------------- finalize: reduce partials, decide, (rare) exact select, combine ----------------
#define HBINS 2048
__global__ void __launch_bounds__(NT) k_fin(
    const float* __restrict__ fy, const float* __restrict__ tmask,
    const float* __restrict__ distf, float* __restrict__ out)
{
    __shared__ double sGlob[8][4];          // cls, norm, ang, angc per warp
    __shared__ double sPos[BB], sNeg[BB], sCnt[BB];
    __shared__ double sPersample[BB];
    __shared__ long long sK[BB];
    __shared__ int   sNeed[BB];
    __shared__ unsigned sHist[HBINS];
    __shared__ unsigned sPrefix;            // selected key prefix bits (left-aligned)
    __shared__ long long sKrem;
    __shared__ double sGt[8];
    __shared__ unsigned long long sAb[8];

    const int tid = threadIdx.x;
    const int wid = tid >> 5, lid = tid & 31;

    // ---- global sums over all 800 partials ----
    double c = 0, nrm = 0, an = 0, anc = 0;
    for (int i = tid; i < NBLK; i += NT) {
        c   += g_p_cls [i];
        nrm += g_p_norm[i];
        an  += g_p_ang [i];
        anc += g_p_angc[i];
    }
    c = warp_red(c); nrm = warp_red(nrm); an = warp_red(an); anc = warp_red(anc);
    if (lid == 0) { sGlob[wid][0]=c; sGlob[wid][1]=nrm; sGlob[wid][2]=an; sGlob[wid][3]=anc; }

    // ---- per-sample sums: warp w handles sample w (100 slots) ----
    if (wid < BB) {
        double ps = 0, ns = 0, pc = 0;
        for (int i = lid; i < BPS; i += 32) {
            int b = wid * BPS + i;
            ps += g_p_pos [b];
            ns += g_p_neg [b];
            pc += g_p_posc[b];
        }
        ps = warp_red(ps); ns = warp_red(ns); pc = warp_red(pc);
        if (lid == 0) { sPos[wid] = ps; sNeg[wid] = ns; sCnt[wid] = pc; }
    }
    __syncthreads();

    // ---- decision per sample ----
    if (tid < BB) {
        int s = tid;
        long long npos = (long long)(sCnt[s] + 0.5);
        long long nneg = (long long)NPIX - npos;
        double posi = 0.0, persample = 0.0;
        int need = 0; long long k = 0;
        if (npos > 0) {
            k = 3 * npos; if (nneg < k) k = nneg;
            posi = sPos[s] / (double)(npos > 1 ? npos : 1);
            if (k <= 0)          persample = posi;
            else if (k == nneg)  persample = posi + sNeg[s] / (double)k;
            else                 need = 1;
        } else {
            k = 100; need = 1; posi = 0.0;   // top-100 over all pre values
        }
        sPersample[s] = persample;
        sNeed[s] = need;
        sK[s] = k;
        // stash posi for slow path in sPos (reuse)
        sPos[s] = posi;
    }
    __syncthreads();

    // ---- rare exact top-k path: 3-level radix select (11/11/10 bits), tie-exact ----
    for (int s = 0; s < BB; s++) {
        if (!sNeed[s]) continue;
        const float* ch1 = fy + ((size_t)s*4 + 1) * NPIX;
        const float* tm  = tmask + (size_t)s * NPIX;
        const float* df  = distf + (size_t)s * NPIX;
        if (tid == 0) { sKrem = sK[s]; sPrefix = 0u; }
        __syncthreads();

        const int lvBits[3]  = {11, 11, 10};
        const int lvShift[3] = {21, 10, 0};
        int nbDone = 0;
        for (int lv = 0; lv < 3; lv++) {
            for (int i = tid; i < HBINS; i += NT) sHist[i] = 0u;
            __syncthreads();
            unsigned pmask = nbDone ? (0xffffffffu << (32 - nbDone)) : 0u;
            unsigned pref  = sPrefix;
            for (int i = tid; i < NPIX; i += NT) {
                unsigned u = key_of(__ldg(ch1+i), __ldg(df+i), __ldg(tm+i));
                if ((u & pmask) == pref)
                    atomicAdd(&sHist[(u >> lvShift[lv]) & ((1u << lvBits[lv]) - 1u)], 1u);
            }
            __syncthreads();
            if (tid == 0) {
                long long krem = sKrem, above = 0;
                int nb = (1 << lvBits[lv]), bsel = 0;
                for (int b = nb - 1; b >= 0; b--) {
                    long long cc = (long long)sHist[b];
                    if (above + cc >= krem) { bsel = b; break; }
                    above += cc;
                }
                sKrem = krem - above;
                sPrefix = sPrefix | ((unsigned)bsel << lvShift[lv]);
            }
            __syncthreads();
            nbDone += lvBits[lv];
        }
        // pivot key = sPrefix; final pass: sum & count of strictly greater
        unsigned pivot_u = sPrefix;
        double gt_local = 0.0; unsigned long long ab_local = 0ull;
        for (int i = tid; i < NPIX; i += NT) {
            float d1 = __ldg(ch1+i), dfv = __ldg(df+i), t = __ldg(tm+i);
            float diff = d1 - dfv;
            float pre  = diff * diff * t;
            unsigned u = (dfv >= 1e-3f) ? 0u : (__float_as_uint(pre) + 1u);
            if (u > pivot_u) { gt_local += (double)pre; ab_local++; }
        }
        double gv = warp_red(gt_local);
        double av = warp_red((double)ab_local);
        if (lid == 0) { sGt[wid] = gv; sAb[wid] = (unsigned long long)(av + 0.5); }
        __syncthreads();
        if (tid == 0) {
            double gts = 0; long long above = 0;
            for (int w = 0; w < 8; w++) { gts += sGt[w]; above += (long long)sAb[w]; }
            long long k = sK[s];
            long long take = k - above;
            float pivotf = __uint_as_float(pivot_u - 1u);   // pivot_u >= 1 guaranteed (neg key)
            double negsum = gts + (double)take * (double)pivotf;
            long long kd = k < 1 ? 1 : k;
            sPersample[s] = sPos[s] + negsum / (double)kd;
        }
        __syncthreads();
    }

    // ---- combine ----
    if (tid == 0) {
        double cls = 0, nr = 0, ag = 0, agc = 0;
        for (int w = 0; w < 8; w++) {
            cls += sGlob[w][0]; nr += sGlob[w][1]; ag += sGlob[w][2]; agc += sGlob[w][3];
        }
        double dis = 0;
        for (int s = 0; s < BB; s++) dis += sPersample[s];
        dis /= (double)BB;
        cls /= (double)BB * (double)NPIX;
        nr  /= (double)BB * (double)HH;         // .sum(-1).mean() over [B,H,W]
        long long ac = (long long)(agc + 0.5); if (ac < 1) ac = 1;
        ag /= (double)ac;
        out[0] = (float)(cls + 3.0 * dis + 0.5 * (nr + ag));
    }
}

// ---------------- launcher: exactly 2 kernels ----------------
extern "C" void kernel_launch(void* const* d_in, const int* in_sizes, int n_in,
                              void* d_out, int out_size) {
    const float* fy    = (const float*)d_in[0];
    const float* tmask = (const float*)d_in[1];
    const int*   trm   = (const int*)  d_in[2];
    const float* distf = (const float*)d_in[3];
    const float* dirf  = (const float*)d_in[4];
    const float* wm    = (const float*)d_in[5];
    float* out = (float*)d_out;

    k_main<<<NBLK, NT>>>(fy, tmask, trm, distf, dirf, wm);
    k_fin<<<1, NT>>>(fy, tmask, distf, out);
}

// round 5
// speedup vs baseline: 1.2483x; 1.0078x over previous
#include <cuda_runtime.h>
#include <stdint.h>
#include <math.h>

// Problem constants
#define BB 8
#define HH 640
#define WW 640
#define NPIX (HH*WW)          // 409600 pixels per sample
#define PPB 4096              // pixels per block in main pass
#define BPS (NPIX/PPB)        // 100 blocks per sample
#define NBLK (BB*BPS)         // 800 blocks
#define NT 256

// -------- device scratch: per-block partial rows (plain stores, no init needed) --------
// layout per block: [cls, pos, neg, posc, norm, ang, angc, pad]
__device__ double g_part[NBLK][8];
__device__ unsigned int g_ticket = 0;   // self-resetting; 0 at module load

__device__ __forceinline__ double warp_red(double v) {
    #pragma unroll
    for (int o = 16; o > 0; o >>= 1) v += __shfl_down_sync(0xffffffffu, v, o);
    return v;
}

// transformed key: pos pixels -> 0 (sorts last), neg -> bits(pre)+1 (monotone, pre>=0)
__device__ __forceinline__ unsigned key_of(float d1, float dfv, float tm) {
    float diff = d1 - dfv;
    float pre  = diff * diff * tm;
    return (dfv >= 1e-3f) ? 0u : (__float_as_uint(pre) + 1u);
}

#define HBINS 2048

// ---------------- single fused kernel ----------------
__global__ void __launch_bounds__(NT) k_all(
    const float* __restrict__ fy,      // [B,4,H,W]
    const float* __restrict__ tmask,   // [B,H,W] float
    const int*   __restrict__ trm,     // [B,H,W] int
    const float* __restrict__ distf,   // [B,H,W]
    const float* __restrict__ dirf,    // [B,2,H,W]
    const float* __restrict__ wm,      // [B,H,W]
    float* __restrict__ out)
{
    const int s    = blockIdx.x / BPS;
    const int tile = blockIdx.x % BPS;
    const int tid  = threadIdx.x;
    const int wid  = tid >> 5, lid = tid & 31;

    // ======== phase 1: fused elementwise pass over this block's 4096 pixels ========
    {
        const float4* c0 = (const float4*)(fy + ((size_t)s*4 + 0) * NPIX);
        const float4* c1 = (const float4*)(fy + ((size_t)s*4 + 1) * NPIX);
        const float4* c2 = (const float4*)(fy + ((size_t)s*4 + 2) * NPIX);
        const float4* c3 = (const float4*)(fy + ((size_t)s*4 + 3) * NPIX);
        const float4* gx4p = (const float4*)(dirf + ((size_t)s*2 + 0) * NPIX);
        const float4* gy4p = (const float4*)(dirf + ((size_t)s*2 + 1) * NPIX);
        const float4* tm4p = (const float4*)(tmask + (size_t)s * NPIX);
        const float4* df4p = (const float4*)(distf + (size_t)s * NPIX);
        const float4* wm4p = (const float4*)(wm    + (size_t)s * NPIX);
        const int4*   tr4p = (const int4*)  (trm   + (size_t)s * NPIX);

        float cls_a = 0.f, pos_a = 0.f, neg_a = 0.f, norm_a = 0.f, ang_a = 0.f;
        int posc = 0, angc = 0;

        #pragma unroll
        for (int j = 0; j < 4; j++) {
            int i4 = tile * (PPB/4) + j * NT + tid;
            float4 p4 = c0[i4], q4 = c1[i4], x4 = c2[i4], y4 = c3[i4];
            float4 g1 = gx4p[i4], g2 = gy4p[i4];
            float4 t4 = tm4p[i4], d4 = df4p[i4], w4 = wm4p[i4];
            int4   r4 = tr4p[i4];

            #pragma unroll
            for (int e = 0; e < 4; e++) {
                float p   = ((const float*)&p4)[e];
                float d1  = ((const float*)&q4)[e];
                float px  = ((const float*)&x4)[e];
                float py  = ((const float*)&y4)[e];
                float gx  = ((const float*)&g1)[e];
                float gy  = ((const float*)&g2)[e];
                float tm  = ((const float*)&t4)[e];
                float dfv = ((const float*)&d4)[e];
                float w   = ((const float*)&w4)[e];
                int   tr  = ((const int*)&r4)[e];

                // cls: masked BCE
                float pc  = fminf(fmaxf(p, 1e-7f), 1.0f - 1e-7f);
                float bce = (tr > 0) ? -logf(pc) : -logf(1.0f - pc);
                cls_a += bce * tm;

                // distance pre-loss + pos/neg split
                float diff = d1 - dfv;
                float pre  = diff * diff * tm;
                bool  pos  = (dfv >= 1e-3f);
                if (pos) { pos_a += pre; posc++; } else { neg_a += pre; }

                // flux: gt normalize (reference eps)
                float sg = gx*gx + gy*gy;
                float gl = sqrtf(sg);
                float ig = 1.0f / (gl + 1e-6f);
                float gtx = gx * ig, gty = gy * ig;
                float ex = px - gtx, ey = py - gty;
                norm_a += w * 0.5f * (ex*ex + ey*ey) * tm;

                // angle (masked)
                if (tm > 0.f && tr > 0) {
                    float sp = px*px + py*py;
                    float pl = sqrtf(sp);
                    float ip = 1.0f / (pl + 1e-6f);
                    float pnx = px * ip, pny = py * ip;
                    float na = sqrtf(pnx*pnx + pny*pny);
                    float nb = sqrtf(gtx*gtx + gty*gty);
                    float cosv = (pnx*gtx + pny*gty) / fmaxf(na*nb, 1e-8f);
                    ang_a += 1.0f - cosv;
                    angc++;
                }
            }
        }

        // block reduction -> per-block partial row
        double v0 = warp_red((double)cls_a);
        double v1 = warp_red((double)pos_a);
        double v2 = warp_red((double)neg_a);
        double v3 = warp_red((double)posc);
        double v4 = warp_red((double)norm_a);
        double v5 = warp_red((double)ang_a);
        double v6 = warp_red((double)angc);

        __shared__ double sh[8][7];
        if (lid == 0) {
            sh[wid][0]=v0; sh[wid][1]=v1; sh[wid][2]=v2; sh[wid][3]=v3;
            sh[wid][4]=v4; sh[wid][5]=v5; sh[wid][6]=v6;
        }
        __syncthreads();
        if (tid == 0) {
            double t[7] = {0,0,0,0,0,0,0};
            #pragma unroll
            for (int k = 0; k < 8; k++)
                #pragma unroll
                for (int q = 0; q < 7; q++) t[q] += sh[k][q];
            #pragma unroll
            for (int q = 0; q < 7; q++) g_part[blockIdx.x][q] = t[q];
            g_part[blockIdx.x][7] = 0.0;
        }
    }

    // ======== phase 2: last block finalizes ========
    __shared__ bool amLast;
    __threadfence();
    if (tid == 0) {
        unsigned t = atomicAdd(&g_ticket, 1u);
        amLast = (t == (unsigned)(NBLK - 1));
        if (amLast) g_ticket = 0u;           // self-reset for graph replay
    }
    __syncthreads();
    if (!amLast) return;

    // --- finalize (single block) ---
    __shared__ double sGlob[8][4];           // cls, norm, ang, angc per warp
    __shared__ double sPos[BB], sNeg[BB], sCnt[BB];
    __shared__ double sPersample[BB];
    __shared__ long long sK[BB];
    __shared__ int   sNeed[BB];
    __shared__ int   sAnyNeed;
    {
        // global sums over all 800 rows (coalesced: consecutive threads read consecutive doubles)
        double c = 0, nrm = 0, an = 0, anc = 0;
        for (int i = tid; i < NBLK; i += NT) {
            const double* r = g_part[i];
            c   += r[0];
            nrm += r[4];
            an  += r[5];
            anc += r[6];
        }
        c = warp_red(c); nrm = warp_red(nrm); an = warp_red(an); anc = warp_red(anc);
        if (lid == 0) { sGlob[wid][0]=c; sGlob[wid][1]=nrm; sGlob[wid][2]=an; sGlob[wid][3]=anc; }

        // per-sample sums: warp w handles sample w (100 rows each)
        if (wid < BB) {
            double ps = 0, ns = 0, pc = 0;
            for (int i = lid; i < BPS; i += 32) {
                const double* r = g_part[wid * BPS + i];
                ps += r[1]; ns += r[2]; pc += r[3];
            }
            ps = warp_red(ps); ns = warp_red(ns); pc = warp_red(pc);
            if (lid == 0) { sPos[wid] = ps; sNeg[wid] = ns; sCnt[wid] = pc; }
        }
        __syncthreads();
    }

    // decision per sample
    if (tid == 0) sAnyNeed = 0;
    __syncthreads();
    if (tid < BB) {
        int ss = tid;
        long long npos = (long long)(sCnt[ss] + 0.5);
        long long nneg = (long long)NPIX - npos;
        double posi = 0.0, persample = 0.0;
        int need = 0; long long k = 0;
        if (npos > 0) {
            k = 3 * npos; if (nneg < k) k = nneg;
            posi = sPos[ss] / (double)(npos > 1 ? npos : 1);
            if (k <= 0)          persample = posi;
            else if (k == nneg)  persample = posi + sNeg[ss] / (double)k;
            else                 { need = 1; atomicAdd(&sAnyNeed, 1); }
        } else {
            k = 100; need = 1; posi = 0.0; atomicAdd(&sAnyNeed, 1);
        }
        sPersample[ss] = persample;
        sNeed[ss] = need;
        sK[ss] = k;
        sPos[ss] = posi;                      // stash for slow path
    }
    __syncthreads();

    // rare exact top-k path: 3-level radix select (11/11/10 bits), tie-exact
    if (sAnyNeed) {
        __shared__ unsigned sHist[HBINS];
        __shared__ unsigned sPrefix;
        __shared__ long long sKrem;
        __shared__ double sGt[8];
        __shared__ unsigned long long sAb[8];
        for (int ss = 0; ss < BB; ss++) {
            if (!sNeed[ss]) continue;
            const float* ch1 = fy + ((size_t)ss*4 + 1) * NPIX;
            const float* tmp = tmask + (size_t)ss * NPIX;
            const float* dfp = distf + (size_t)ss * NPIX;
            if (tid == 0) { sKrem = sK[ss]; sPrefix = 0u; }
            __syncthreads();

            const int lvBits[3]  = {11, 11, 10};
            const int lvShift[3] = {21, 10, 0};
            int nbDone = 0;
            for (int lv = 0; lv < 3; lv++) {
                for (int i = tid; i < HBINS; i += NT) sHist[i] = 0u;
                __syncthreads();
                unsigned pmask = nbDone ? (0xffffffffu << (32 - nbDone)) : 0u;
                unsigned pref  = sPrefix;
                for (int i = tid; i < NPIX; i += NT) {
                    unsigned u = key_of(__ldg(ch1+i), __ldg(dfp+i), __ldg(tmp+i));
                    if ((u & pmask) == pref)
                        atomicAdd(&sHist[(u >> lvShift[lv]) & ((1u << lvBits[lv]) - 1u)], 1u);
                }
                __syncthreads();
                if (tid == 0) {
                    long long krem = sKrem, above = 0;
                    int nb = (1 << lvBits[lv]), bsel = 0;
                    for (int b = nb - 1; b >= 0; b--) {
                        long long cc = (long long)sHist[b];
                        if (above + cc >= krem) { bsel = b; break; }
                        above += cc;
                    }
                    sKrem = krem - above;
                    sPrefix = sPrefix | ((unsigned)bsel << lvShift[lv]);
                }
                __syncthreads();
                nbDone += lvBits[lv];
            }
            unsigned pivot_u = sPrefix;
            double gt_local = 0.0; unsigned long long ab_local = 0ull;
            for (int i = tid; i < NPIX; i += NT) {
                float d1 = __ldg(ch1+i), dfv = __ldg(dfp+i), t = __ldg(tmp+i);
                float diff = d1 - dfv;
                float pre  = diff * diff * t;
                unsigned u = (dfv >= 1e-3f) ? 0u : (__float_as_uint(pre) + 1u);
                if (u > pivot_u) { gt_local += (double)pre; ab_local++; }
            }
            double gv = warp_red(gt_local);
            double av = warp_red((double)ab_local);
            if (lid == 0) { sGt[wid] = gv; sAb[wid] = (unsigned long long)(av + 0.5); }
            __syncthreads();
            if (tid == 0) {
                double gts = 0; long long above = 0;
                for (int w = 0; w < 8; w++) { gts += sGt[w]; above += (long long)sAb[w]; }
                long long k = sK[ss];
                long long take = k - above;
                float pivotf = __uint_as_float(pivot_u - 1u);
                double negsum = gts + (double)take * (double)pivotf;
                long long kd = k < 1 ? 1 : k;
                sPersample[ss] = sPos[ss] + negsum / (double)kd;
            }
            __syncthreads();
        }
    }

    // combine
    if (tid == 0) {
        double cls = 0, nr = 0, ag = 0, agc = 0;
        for (int w = 0; w < 8; w++) {
            cls += sGlob[w][0]; nr += sGlob[w][1]; ag += sGlob[w][2]; agc += sGlob[w][3];
        }
        double dis = 0;
        for (int ss = 0; ss < BB; ss++) dis += sPersample[ss];
        dis /= (double)BB;
        cls /= (double)BB * (double)NPIX;
        nr  /= (double)BB * (double)HH;       // .sum(-1).mean() over [B,H,W]
        long long ac = (long long)(agc + 0.5); if (ac < 1) ac = 1;
        ag /= (double)ac;
        out[0] = (float)(cls + 3.0 * dis + 0.5 * (nr + ag));
    }
}

// ---------------- launcher: one kernel ----------------
extern "C" void kernel_launch(void* const* d_in, const int* in_sizes, int n_in,
                              void* d_out, int out_size) {
    const float* fy    = (const float*)d_in[0];
    const float* tmask = (const float*)d_in[1];
    const int*   trm   = (const int*)  d_in[2];
    const float* distf = (const float*)d_in[3];
    const float* dirf  = (const float*)d_in[4];
    const float* wm    = (const float*)d_in[5];
    float* out = (float*)d_out;

    k_all<<<NBLK, NT>>>(fy, tmask, trm, distf, dirf, wm, out);
}